// round 13
// baseline (speedup 1.0000x reference)
#include <cuda_runtime.h>

// Adder2D: out[n,co,h,w] = -sum_{ci,kh,kw} |x_pad - w|
// R13 = R12 math (ci-packed: FADD2 diff -> 2xLOP3 abs -> FADD2 acc, CO_T=8, 2 px rows)
// + cp.async double-buffered staging: x stored as scalar planes, both slices' copies
// issued at block start (slice1 latency fully hidden). Halo pre-zeroed once.
// Block = 16 ci (2 slices of 8); ci-split x4 combined via atomicAdd.

#define CI_   64
#define CO_   64
#define H_    32
#define W_    32

#define CO_T     8
#define TILE_H   8      // thread owns rows 2ty, 2ty+1
#define SLICE    8      // ci per slice
#define NSLICE   2      // slices per block (16 ci) -> ci-split x4
#define THREADS  128

#define XS_ROWS  10     // TILE_H + 2
#define XS_COLS  34     // W + 2
#define PLANE    (XS_ROWS * XS_COLS)          // 340 floats
#define BUFSZ    (SLICE * PLANE)              // 2720 floats per buffer

typedef unsigned long long u64;

__device__ __forceinline__ u64 f2add(u64 a, u64 b) {
    u64 r;
    asm("add.rn.f32x2 %0, %1, %2;" : "=l"(r) : "l"(a), "l"(b));
    return r;
}

__device__ __forceinline__ u64 packff(float lo, float hi) {
    u64 r;
    asm("mov.b64 %0, {%1, %2};" : "=l"(r) : "f"(lo), "f"(hi));
    return r;
}

__device__ __forceinline__ float u64lo(u64 v) {
    return __uint_as_float((unsigned int)(v & 0xffffffffu));
}
__device__ __forceinline__ float u64hi(u64 v) {
    return __uint_as_float((unsigned int)(v >> 32));
}

__device__ __forceinline__ void cp_async8(unsigned int smem_addr, const void* gptr) {
    asm volatile("cp.async.ca.shared.global [%0], [%1], 8;\n"
                 :: "r"(smem_addr), "l"(gptr));
}

__global__ void __launch_bounds__(THREADS, 8)
adder2d_kernel(const float* __restrict__ x,
               const float* __restrict__ w,
               float* __restrict__ out)
{
    // x planes, scalar f32, 1-float lead pad so interior (col>=1, 8B chunks) is 8B-aligned.
    __shared__ float xsf[2 * BUFSZ + 2];
    // ci-pair packed negated weights: [slice][q][tap][co], co contiguous, 16B aligned.
    __shared__ __align__(16) u64 ws2[NSLICE][SLICE / 2][9][CO_T];

    const int tid = threadIdx.x;
    const int tx  = tid & 31;
    const int ty  = tid >> 5;
    const int h0  = blockIdx.x * TILE_H;
    const int co0 = blockIdx.y * CO_T;
    const int n   = blockIdx.z >> 2;
    const int ci0 = (blockIdx.z & 3) * (SLICE * NSLICE);

    const float* xn = x + (size_t)n * (CI_ * H_ * W_);

    // ---- zero halo cells (cols 0/33 everywhere; full rows where gh is out of range) ----
    for (int i = tid; i < 2 * SLICE * XS_ROWS; i += THREADS) {   // 160 row instances
        const int b = i / (SLICE * XS_ROWS);
        const int j = i - b * (SLICE * XS_ROWS);
        const int p = j / XS_ROWS;
        const int r = j - p * XS_ROWS;
        float* row = &xsf[1 + b * BUFSZ + p * PLANE + r * XS_COLS];
        const int gh = h0 + r - 1;
        if ((unsigned)gh >= (unsigned)H_) {
            #pragma unroll
            for (int c = 0; c < XS_COLS; ++c) row[c] = 0.0f;
        } else {
            row[0] = 0.0f;
            row[XS_COLS - 1] = 0.0f;
        }
    }

    // ---- issue cp.async for BOTH slices immediately (slice1 fully hidden) ----
    #pragma unroll
    for (int s = 0; s < NSLICE; ++s) {
        const float* xs_src = xn + (size_t)(ci0 + s * SLICE) * (H_ * W_);
        // 8 planes x 10 rows x 16 8-byte chunks = 1280 ops
        for (int i = tid; i < SLICE * XS_ROWS * 16; i += THREADS) {
            const int p = i / (XS_ROWS * 16);
            const int j = i - p * (XS_ROWS * 16);
            const int r = j / 16;
            const int k = j - r * 16;
            const int gh = h0 + r - 1;
            if ((unsigned)gh < (unsigned)H_) {
                float* dst = &xsf[1 + s * BUFSZ + p * PLANE + r * XS_COLS + 1 + 2 * k];
                unsigned int da = (unsigned int)__cvta_generic_to_shared(dst);
                cp_async8(da, xs_src + p * (H_ * W_) + gh * W_ + 2 * k);
            }
        }
        asm volatile("cp.async.commit_group;\n" ::: "memory");
    }

    // ---- stage w for both slices (LDG->STS, overlaps the cp.async latency) ----
    for (int i = tid; i < NSLICE * (SLICE / 2) * 9 * CO_T; i += THREADS) {   // 576
        const int s  = i / ((SLICE / 2) * 9 * CO_T);
        const int r1 = i - s * ((SLICE / 2) * 9 * CO_T);
        const int q  = r1 / (9 * CO_T);
        const int r2 = r1 - q * (9 * CO_T);
        const int tap = r2 / CO_T;
        const int co  = r2 - tap * CO_T;
        const int cib = ci0 + s * SLICE + 2 * q;
        const float w0 = w[(co0 + co) * (CI_ * 9) + (cib + 0) * 9 + tap];
        const float w1 = w[(co0 + co) * (CI_ * 9) + (cib + 1) * 9 + tap];
        ws2[s][q][tap][co] = packff(-w0, -w1);
    }

    // accumulators: [pixel-row(2)][co(8)], halves = even/odd ci partial sums (16 ci total)
    u64 acc[2][CO_T];
    #pragma unroll
    for (int p = 0; p < 2; ++p)
        #pragma unroll
        for (int co = 0; co < CO_T; ++co) acc[p][co] = 0ull;

    const int px = tx;
    const int ry = 2 * ty;

    #pragma unroll
    for (int s = 0; s < NSLICE; ++s) {
        // wait: slice s copies complete (allow NSLICE-1-s groups still pending)
        if (s == 0) asm volatile("cp.async.wait_group 1;\n" ::: "memory");
        else        asm volatile("cp.async.wait_group 0;\n" ::: "memory");
        __syncthreads();

        const int xb = 1 + s * BUFSZ;
        #pragma unroll 2
        for (int q = 0; q < SLICE / 2; ++q) {
            const int pe = xb + (2 * q + 0) * PLANE;
            const int po = xb + (2 * q + 1) * PLANE;
            #pragma unroll
            for (int kh = 0; kh < 3; ++kh) {
                #pragma unroll
                for (int kw = 0; kw < 3; ++kw) {
                    const int c0 = (ry + 0 + kh) * XS_COLS + px + kw;
                    const int c1 = (ry + 1 + kh) * XS_COLS + px + kw;
                    const u64 x0 = packff(xsf[pe + c0], xsf[po + c0]);  // 2x LDS.32 -> pair
                    const u64 x1 = packff(xsf[pe + c1], xsf[po + c1]);
                    const int tap = kh * 3 + kw;
                    #pragma unroll
                    for (int cp = 0; cp < CO_T / 2; ++cp) {
                        const ulonglong2 wv = *(const ulonglong2*)&ws2[s][q][tap][2 * cp];
                        u64 d0 = f2add(x0, wv.x);               // fma pipe
                        u64 d1 = f2add(x1, wv.x);
                        d0 &= 0x7fffffff7fffffffULL;            // alu pipe (2x LOP3)
                        d1 &= 0x7fffffff7fffffffULL;
                        acc[0][2 * cp + 0] = f2add(acc[0][2 * cp + 0], d0);
                        acc[1][2 * cp + 0] = f2add(acc[1][2 * cp + 0], d1);
                        u64 e0 = f2add(x0, wv.y);
                        u64 e1 = f2add(x1, wv.y);
                        e0 &= 0x7fffffff7fffffffULL;
                        e1 &= 0x7fffffff7fffffffULL;
                        acc[0][2 * cp + 1] = f2add(acc[0][2 * cp + 1], e0);
                        acc[1][2 * cp + 1] = f2add(acc[1][2 * cp + 1], e1);
                    }
                }
            }
        }
    }

    // ---- epilogue: horizontal add (even+odd ci), atomic combine (out pre-zeroed) ----
    #pragma unroll
    for (int co = 0; co < CO_T; ++co) {
        #pragma unroll
        for (int p = 0; p < 2; ++p) {
            const float ssum = u64lo(acc[p][co]) + u64hi(acc[p][co]);
            const int h = h0 + ry + p;
            atomicAdd(&out[(((size_t)n * CO_ + (co0 + co)) * H_ + h) * W_ + px], -ssum);
        }
    }
}

extern "C" void kernel_launch(void* const* d_in, const int* in_sizes, int n_in,
                              void* d_out, int out_size)
{
    const float* x = (const float*)d_in[0];
    const float* w = (const float*)d_in[1];
    float* out = (float*)d_out;

    const int N = in_sizes[0] / (CI_ * H_ * W_);   // 16

    cudaMemsetAsync(d_out, 0, (size_t)out_size * sizeof(float));

    dim3 grid(H_ / TILE_H, CO_ / CO_T, N * 4);     // (4, 8, 64) = 2048 blocks
    adder2d_kernel<<<grid, THREADS>>>(x, w, out);
}

// round 14
// speedup vs baseline: 1.0325x; 1.0325x over previous
#include <cuda_runtime.h>

// Adder2D: out[n,co,h,w] = -sum_{ci,kh,kw} |x_pad - w|
// R14 = R13 (cp.async double-buffered, ci-packed FADD2/LOP3 math, CO_T=8)
// + PREPASS kernel packs ci-pairs into __device__ scratch so the main kernel
//   cp.asyncs already-packed u64 pairs (16B chunks) and reads x with ONE LDS.64
//   (no LDS.32 pairs, no packff MOVs on the alu pipe).

#define CI_   64
#define CO_   64
#define H_    32
#define W_    32
#define NMAX_ 16

#define CO_T     8
#define TILE_H   8      // thread owns rows 2ty, 2ty+1
#define SLICE_Q  4      // ci-pairs per slice (= 8 ci)
#define NSLICE   2      // slices per block (16 ci) -> ci-split x4
#define THREADS  128

#define XS_ROWS  10     // TILE_H + 2
#define XS_COLS  34     // W + 2
#define PLANE    (XS_ROWS * XS_COLS)          // 340 u64
#define BUFSZ    (SLICE_Q * PLANE)            // 1360 u64 per slice buffer

typedef unsigned long long u64;

// packed x scratch: [n][q=ci/2][h][w] = pack(x[2q], x[2q+1]) -- 4MB
__device__ u64 xpack_buf[NMAX_ * (CI_ / 2) * H_ * W_];

__device__ __forceinline__ u64 f2add(u64 a, u64 b) {
    u64 r;
    asm("add.rn.f32x2 %0, %1, %2;" : "=l"(r) : "l"(a), "l"(b));
    return r;
}

__device__ __forceinline__ u64 packff(float lo, float hi) {
    u64 r;
    asm("mov.b64 %0, {%1, %2};" : "=l"(r) : "f"(lo), "f"(hi));
    return r;
}

__device__ __forceinline__ float u64lo(u64 v) {
    return __uint_as_float((unsigned int)(v & 0xffffffffu));
}
__device__ __forceinline__ float u64hi(u64 v) {
    return __uint_as_float((unsigned int)(v >> 32));
}

__device__ __forceinline__ void cp_async16(unsigned int smem_addr, const void* gptr) {
    asm volatile("cp.async.ca.shared.global [%0], [%1], 16;\n"
                 :: "r"(smem_addr), "l"(gptr));
}

// ---------------- prepass: pack adjacent ci planes ----------------
__global__ void __launch_bounds__(256)
pack_kernel(const float* __restrict__ x, int total)
{
    const int i = blockIdx.x * 256 + threadIdx.x;
    if (i >= total) return;
    const int hw = i & (H_ * W_ - 1);
    const int q  = (i >> 10) & (CI_ / 2 - 1);
    const int n  = i >> 15;
    const float* base = x + ((size_t)n * CI_ + 2 * q) * (H_ * W_) + hw;
    xpack_buf[i] = packff(base[0], base[H_ * W_]);
}

// ---------------- main kernel ----------------
__global__ void __launch_bounds__(THREADS, 8)
adder2d_kernel(const float* __restrict__ w,
               float* __restrict__ out)
{
    // packed x planes; LEAD=1 so interior (col>=1) chunks are 16B-aligned
    __shared__ u64 xq[2 * BUFSZ + 2];
    // ci-pair packed negated weights: [slice][q][tap][co], co contiguous, 16B aligned
    __shared__ __align__(16) u64 ws2[NSLICE][SLICE_Q][9][CO_T];

    const int tid = threadIdx.x;
    const int tx  = tid & 31;
    const int ty  = tid >> 5;
    const int h0  = blockIdx.x * TILE_H;
    const int co0 = blockIdx.y * CO_T;
    const int n   = blockIdx.z >> 2;
    const int q0  = (blockIdx.z & 3) * (SLICE_Q * NSLICE);   // first ci-pair index

    const u64* xp = xpack_buf + (size_t)n * (CI_ / 2) * (H_ * W_);

    // ---- zero halo (cols 0/33 per row; full rows where gh out of range) ----
    for (int i = tid; i < NSLICE * SLICE_Q * XS_ROWS; i += THREADS) {   // 80 rows
        const int s  = i / (SLICE_Q * XS_ROWS);
        const int j  = i - s * (SLICE_Q * XS_ROWS);
        const int ql = j / XS_ROWS;
        const int r  = j - ql * XS_ROWS;
        u64* row = &xq[1 + s * BUFSZ + ql * PLANE + r * XS_COLS];
        const int gh = h0 + r - 1;
        if ((unsigned)gh >= (unsigned)H_) {
            #pragma unroll
            for (int c = 0; c < XS_COLS; ++c) row[c] = 0ull;
        } else {
            row[0] = 0ull;
            row[XS_COLS - 1] = 0ull;
        }
    }

    // ---- issue cp.async for BOTH slices (16B chunks = 2 packed pairs each) ----
    #pragma unroll
    for (int s = 0; s < NSLICE; ++s) {
        // 4 planes x 10 rows x 16 chunks = 640 ops per slice
        for (int i = tid; i < SLICE_Q * XS_ROWS * 16; i += THREADS) {
            const int ql = i / (XS_ROWS * 16);
            const int j  = i - ql * (XS_ROWS * 16);
            const int r  = j / 16;
            const int k  = j - r * 16;
            const int gh = h0 + r - 1;
            if ((unsigned)gh < (unsigned)H_) {
                // dst u64 index: 1 + s*BUFSZ + ql*PLANE + r*XS_COLS + 1 + 2k  (even -> 16B aligned)
                u64* dst = &xq[2 + s * BUFSZ + ql * PLANE + r * XS_COLS + 2 * k];
                unsigned int da = (unsigned int)__cvta_generic_to_shared(dst);
                cp_async16(da, xp + (size_t)(q0 + s * SLICE_Q + ql) * (H_ * W_) + gh * W_ + 2 * k);
            }
        }
        asm volatile("cp.async.commit_group;\n" ::: "memory");
    }

    // ---- stage w for both slices (overlaps cp.async latency) ----
    for (int i = tid; i < NSLICE * SLICE_Q * 9 * CO_T; i += THREADS) {   // 576
        const int s  = i / (SLICE_Q * 9 * CO_T);
        const int r1 = i - s * (SLICE_Q * 9 * CO_T);
        const int ql = r1 / (9 * CO_T);
        const int r2 = r1 - ql * (9 * CO_T);
        const int tap = r2 / CO_T;
        const int co  = r2 - tap * CO_T;
        const int cib = 2 * (q0 + s * SLICE_Q + ql);
        const float w0 = w[(co0 + co) * (CI_ * 9) + (cib + 0) * 9 + tap];
        const float w1 = w[(co0 + co) * (CI_ * 9) + (cib + 1) * 9 + tap];
        ws2[s][ql][tap][co] = packff(-w0, -w1);
    }

    // accumulators: [pixel-row(2)][co(8)], halves = even/odd ci partial sums
    u64 acc[2][CO_T];
    #pragma unroll
    for (int p = 0; p < 2; ++p)
        #pragma unroll
        for (int co = 0; co < CO_T; ++co) acc[p][co] = 0ull;

    const int px = tx;
    const int ry = 2 * ty;

    #pragma unroll
    for (int s = 0; s < NSLICE; ++s) {
        if (s == 0) asm volatile("cp.async.wait_group 1;\n" ::: "memory");
        else        asm volatile("cp.async.wait_group 0;\n" ::: "memory");
        __syncthreads();

        const int xb = 1 + s * BUFSZ;
        #pragma unroll 2
        for (int ql = 0; ql < SLICE_Q; ++ql) {
            const int pb = xb + ql * PLANE;
            #pragma unroll
            for (int kh = 0; kh < 3; ++kh) {
                #pragma unroll
                for (int kw = 0; kw < 3; ++kw) {
                    const u64 x0 = xq[pb + (ry + 0 + kh) * XS_COLS + px + kw];  // LDS.64
                    const u64 x1 = xq[pb + (ry + 1 + kh) * XS_COLS + px + kw];  // LDS.64
                    const int tap = kh * 3 + kw;
                    #pragma unroll
                    for (int cp = 0; cp < CO_T / 2; ++cp) {
                        const ulonglong2 wv = *(const ulonglong2*)&ws2[s][ql][tap][2 * cp];
                        u64 d0 = f2add(x0, wv.x);               // fma pipe
                        u64 d1 = f2add(x1, wv.x);
                        d0 &= 0x7fffffff7fffffffULL;            // alu pipe (2x LOP3)
                        d1 &= 0x7fffffff7fffffffULL;
                        acc[0][2 * cp + 0] = f2add(acc[0][2 * cp + 0], d0);
                        acc[1][2 * cp + 0] = f2add(acc[1][2 * cp + 0], d1);
                        u64 e0 = f2add(x0, wv.y);
                        u64 e1 = f2add(x1, wv.y);
                        e0 &= 0x7fffffff7fffffffULL;
                        e1 &= 0x7fffffff7fffffffULL;
                        acc[0][2 * cp + 1] = f2add(acc[0][2 * cp + 1], e0);
                        acc[1][2 * cp + 1] = f2add(acc[1][2 * cp + 1], e1);
                    }
                }
            }
        }
    }

    // ---- epilogue: horizontal add (even+odd ci), atomic combine (out pre-zeroed) ----
    #pragma unroll
    for (int co = 0; co < CO_T; ++co) {
        #pragma unroll
        for (int p = 0; p < 2; ++p) {
            const float ssum = u64lo(acc[p][co]) + u64hi(acc[p][co]);
            const int h = h0 + ry + p;
            atomicAdd(&out[(((size_t)n * CO_ + (co0 + co)) * H_ + h) * W_ + px], -ssum);
        }
    }
}

extern "C" void kernel_launch(void* const* d_in, const int* in_sizes, int n_in,
                              void* d_out, int out_size)
{
    const float* x = (const float*)d_in[0];
    const float* w = (const float*)d_in[1];
    float* out = (float*)d_out;

    const int N = in_sizes[0] / (CI_ * H_ * W_);   // 16
    const int total = N * (CI_ / 2) * H_ * W_;     // 524288 packed pairs

    cudaMemsetAsync(d_out, 0, (size_t)out_size * sizeof(float));
    pack_kernel<<<(total + 255) / 256, 256>>>(x, total);

    dim3 grid(H_ / TILE_H, CO_ / CO_T, N * 4);     // (4, 8, 64) = 2048 blocks
    adder2d_kernel<<<grid, THREADS>>>(w, out);
}